// round 14
// baseline (speedup 1.0000x reference)
#include <cuda_runtime.h>
#include <math.h>
#include <float.h>

#define BATCH   4096
#define NPART   100
#define PSIZE   64
#define CTX     64
#define H1      256
#define H2      256
#define F3IN    320
#define F3OUT   512
#define F4OUT   256
#define F5OUT   128
#define F6OUT   32
#define HID     32
#define NLAYER  6
#define VOCAB   361
#define TSTEPS  24
#define TOPK    8

typedef unsigned long long ull;

// scratch (device globals: allowed; no runtime allocation)
__device__ float g_pooled[BATCH * H2];   // 4 MB
__device__ float g_z[BATCH * F6OUT];     // 0.5 MB
__device__ float g_w1hi[PSIZE * H1];     // 64 KB  tf32-rounded hi plane of w1
__device__ float g_w1lo[PSIZE * H1];     // 64 KB  tf32 lo plane
__device__ float g_w2hi[H1 * H1];        // 256 KB
__device__ float g_w2lo[H1 * H1];        // 256 KB

// ---------------- f32x2 packed helpers (lstm uses these) -------------------
__device__ __forceinline__ ull ffma2(ull a, ull b, ull c) {
    ull d;
    asm("fma.rn.f32x2 %0, %1, %2, %3;" : "=l"(d) : "l"(a), "l"(b), "l"(c));
    return d;
}
__device__ __forceinline__ ull pack_dup(float v) {
    ull d;
    unsigned r = __float_as_uint(v);
    asm("mov.b64 %0, {%1, %2};" : "=l"(d) : "r"(r), "r"(r));
    return d;
}

// ---------------- tf32 helpers --------------------------------------------
__device__ __forceinline__ unsigned f2tf(float a) {
    unsigned r;
    asm("cvt.rna.tf32.f32 %0, %1;" : "=r"(r) : "f"(a));
    return r;
}

// m16n8k8 tf32 mma (baseline PTX, sm_80+, valid on plain sm_103 target)
#define MMA_TF32(d0, d1, d2, d3, a0, a1, a2, a3, b0, b1)                    \
    asm volatile("mma.sync.aligned.m16n8k8.row.col.f32.tf32.tf32.f32 "      \
                 "{%0,%1,%2,%3}, {%4,%5,%6,%7}, {%8,%9}, {%0,%1,%2,%3};"    \
                 : "+f"(d0), "+f"(d1), "+f"(d2), "+f"(d3)                   \
                 : "r"(a0), "r"(a1), "r"(a2), "r"(a3), "r"(b0), "r"(b1))

// ---------------------------------------------------------------------------
// Kernel 0: split w1/w2 into tf32 hi/lo planes (same [k][n] layout).
// ---------------------------------------------------------------------------
__global__ void prep_tf(const float* __restrict__ w1, const float* __restrict__ w2)
{
    const int i = blockIdx.x * 256 + threadIdx.x;   // 65536 threads
    if (i < PSIZE * H1) {
        const float v  = w1[i];
        const unsigned h = f2tf(v);
        g_w1hi[i] = __uint_as_float(h);
        g_w1lo[i] = __uint_as_float(f2tf(v - __uint_as_float(h)));
    }
    if (i < H1 * H1) {
        const float v  = w2[i];
        const unsigned h = f2tf(v);
        g_w2hi[i] = __uint_as_float(h);
        g_w2lo[i] = __uint_as_float(f2tf(v - __uint_as_float(h)));
    }
}

// ---------------------------------------------------------------------------
// Kernel 1: 3xTF32 mma.sync encoder. 1 CTA/sample, 256 thr = 8 warps.
// Warp w owns rows w*16..w*16+15 for the whole pipeline (no CTA barriers in
// the mainloop). fc1: K=64, 4 N-passes -> h fp32 smem. fc2: K=256, 2 N-halves
// of 128 (64 accum regs), A split on the fly, B from prepped gmem planes.
// Epilogue: bias+relu+row-masked mean-pool.
// ---------------------------------------------------------------------------
#define X_STRIDE 68
#define H_STRIDE 260
#define ENC_SMEM_FLOATS (2 * 128 * X_STRIDE + 128 * H_STRIDE)
#define ENC_SMEM_BYTES  (ENC_SMEM_FLOATS * 4)   // 202752

__global__ __launch_bounds__(256, 1) void enc_tf(
    const float* __restrict__ x,
    const float* __restrict__ b1, const float* __restrict__ b2)
{
    extern __shared__ float sm[];
    float* xhi = sm;                          // [128][X_STRIDE]
    float* xlo = sm + 128 * X_STRIDE;
    float* hsm = sm + 2 * 128 * X_STRIDE;     // [128][H_STRIDE] fp32 h1

    __shared__ float pool[8][H1];             // 8 KB

    const int b    = blockIdx.x;
    const int tid  = threadIdx.x;
    const int w    = tid >> 5;
    const int lane = tid & 31;

    // ---- stage x split planes (rows >= 100 zeroed) ----
    for (int i = tid; i < 128 * PSIZE; i += 256) {
        const int row = i >> 6, k = i & 63;
        float v = 0.f;
        if (row < NPART) v = x[(size_t)b * (NPART * PSIZE) + row * PSIZE + k];
        const unsigned h = f2tf(v);
        xhi[row * X_STRIDE + k] = __uint_as_float(h);
        xlo[row * X_STRIDE + k] = __uint_as_float(f2tf(v - __uint_as_float(h)));
    }
    __syncthreads();

    const int wrow = w * 16;
    const int rq   = lane >> 2;       // 0..7
    const int kq   = lane & 3;        // 0..3

    // =====================  fc1: 4 N-passes of 64  =====================
    for (int np = 0; np < 4; np++) {
        const int nb = np * 64;
        float d1[8][4];
        #pragma unroll
        for (int nt = 0; nt < 8; nt++)
            d1[nt][0] = d1[nt][1] = d1[nt][2] = d1[nt][3] = 0.f;

        #pragma unroll
        for (int ks = 0; ks < 8; ks++) {
            const int kb = ks * 8;
            const int r0 = (wrow + rq) * X_STRIDE;
            const int r1 = (wrow + rq + 8) * X_STRIDE;
            const unsigned ah0 = __float_as_uint(xhi[r0 + kb + kq]);
            const unsigned ah1 = __float_as_uint(xhi[r1 + kb + kq]);
            const unsigned ah2 = __float_as_uint(xhi[r0 + kb + kq + 4]);
            const unsigned ah3 = __float_as_uint(xhi[r1 + kb + kq + 4]);
            const unsigned al0 = __float_as_uint(xlo[r0 + kb + kq]);
            const unsigned al1 = __float_as_uint(xlo[r1 + kb + kq]);
            const unsigned al2 = __float_as_uint(xlo[r0 + kb + kq + 4]);
            const unsigned al3 = __float_as_uint(xlo[r1 + kb + kq + 4]);
            #pragma unroll
            for (int nt = 0; nt < 8; nt++) {
                const int col = nb + nt * 8 + rq;
                const int kr0 = (kb + kq) * H1 + col;
                const int kr1 = (kb + kq + 4) * H1 + col;
                const unsigned bh0 = __float_as_uint(g_w1hi[kr0]);
                const unsigned bh1 = __float_as_uint(g_w1hi[kr1]);
                const unsigned bl0 = __float_as_uint(g_w1lo[kr0]);
                const unsigned bl1 = __float_as_uint(g_w1lo[kr1]);
                MMA_TF32(d1[nt][0], d1[nt][1], d1[nt][2], d1[nt][3],
                         ah0, ah1, ah2, ah3, bl0, bl1);           // hi*lo
                MMA_TF32(d1[nt][0], d1[nt][1], d1[nt][2], d1[nt][3],
                         al0, al1, al2, al3, bh0, bh1);           // lo*hi
                MMA_TF32(d1[nt][0], d1[nt][1], d1[nt][2], d1[nt][3],
                         ah0, ah1, ah2, ah3, bh0, bh1);           // hi*hi
            }
        }

        // bias + relu -> h smem (fp32)
        {
            const int r0 = wrow + rq, r1 = r0 + 8;
            #pragma unroll
            for (int nt = 0; nt < 8; nt++) {
                const int c0 = nb + nt * 8 + 2 * kq;
                const float bb0 = b1[c0], bb1 = b1[c0 + 1];
                hsm[r0 * H_STRIDE + c0]     = fmaxf(d1[nt][0] + bb0, 0.f);
                hsm[r0 * H_STRIDE + c0 + 1] = fmaxf(d1[nt][1] + bb1, 0.f);
                hsm[r1 * H_STRIDE + c0]     = fmaxf(d1[nt][2] + bb0, 0.f);
                hsm[r1 * H_STRIDE + c0 + 1] = fmaxf(d1[nt][3] + bb1, 0.f);
            }
        }
        __syncwarp();
    }

    // =====================  fc2: 2 N-halves of 128  =====================
    for (int half = 0; half < 2; half++) {
        const int nb = half * 128;
        float d2[16][4];
        #pragma unroll
        for (int nt = 0; nt < 16; nt++)
            d2[nt][0] = d2[nt][1] = d2[nt][2] = d2[nt][3] = 0.f;

        for (int kbi = 0; kbi < 32; kbi++) {
            const int kb = kbi * 8;
            const int r0 = (wrow + rq) * H_STRIDE;
            const int r1 = (wrow + rq + 8) * H_STRIDE;
            const float v0 = hsm[r0 + kb + kq];
            const float v1 = hsm[r1 + kb + kq];
            const float v2 = hsm[r0 + kb + kq + 4];
            const float v3 = hsm[r1 + kb + kq + 4];
            const unsigned ah0 = f2tf(v0), ah1 = f2tf(v1);
            const unsigned ah2 = f2tf(v2), ah3 = f2tf(v3);
            const unsigned al0 = f2tf(v0 - __uint_as_float(ah0));
            const unsigned al1 = f2tf(v1 - __uint_as_float(ah1));
            const unsigned al2 = f2tf(v2 - __uint_as_float(ah2));
            const unsigned al3 = f2tf(v3 - __uint_as_float(ah3));
            #pragma unroll
            for (int nt = 0; nt < 16; nt++) {
                const int col = nb + nt * 8 + rq;
                const int kr0 = (kb + kq) * H1 + col;
                const int kr1 = (kb + kq + 4) * H1 + col;
                const unsigned bh0 = __float_as_uint(g_w2hi[kr0]);
                const unsigned bh1 = __float_as_uint(g_w2hi[kr1]);
                const unsigned bl0 = __float_as_uint(g_w2lo[kr0]);
                const unsigned bl1 = __float_as_uint(g_w2lo[kr1]);
                MMA_TF32(d2[nt][0], d2[nt][1], d2[nt][2], d2[nt][3],
                         ah0, ah1, ah2, ah3, bl0, bl1);
                MMA_TF32(d2[nt][0], d2[nt][1], d2[nt][2], d2[nt][3],
                         al0, al1, al2, al3, bh0, bh1);
                MMA_TF32(d2[nt][0], d2[nt][1], d2[nt][2], d2[nt][3],
                         ah0, ah1, ah2, ah3, bh0, bh1);
            }
        }

        // epilogue for this half: bias + relu + masked row-pool
        {
            const int r0 = wrow + rq, r1 = r0 + 8;
            const bool m0 = (r0 < NPART), m1 = (r1 < NPART);
            #pragma unroll
            for (int nt = 0; nt < 16; nt++) {
                const int c0 = nb + nt * 8 + 2 * kq;
                const float bb0 = b2[c0], bb1 = b2[c0 + 1];
                float s0 = (m0 ? fmaxf(d2[nt][0] + bb0, 0.f) : 0.f)
                         + (m1 ? fmaxf(d2[nt][2] + bb0, 0.f) : 0.f);
                float s1 = (m0 ? fmaxf(d2[nt][1] + bb1, 0.f) : 0.f)
                         + (m1 ? fmaxf(d2[nt][3] + bb1, 0.f) : 0.f);
                #pragma unroll
                for (int off = 16; off >= 4; off >>= 1) {
                    s0 += __shfl_xor_sync(0xffffffffu, s0, off);
                    s1 += __shfl_xor_sync(0xffffffffu, s1, off);
                }
                if (lane < 4) {
                    pool[w][c0]     = s0;
                    pool[w][c0 + 1] = s1;
                }
            }
        }
    }
    __syncthreads();

    // final cross-warp pool reduce + mean
    {
        float s = 0.f;
        #pragma unroll
        for (int ww = 0; ww < 8; ww++) s += pool[ww][tid];
        g_pooled[(size_t)b * H2 + tid] = s * 0.01f;
    }
}

// ---------------------------------------------------------------------------
// Kernel 2: fc3..fc6 head. 8 samples per CTA, 256 threads. (frozen R11)
// ---------------------------------------------------------------------------
__global__ __launch_bounds__(256) void head_kernel(
    const float* __restrict__ c,
    const float* __restrict__ w3, const float* __restrict__ b3,
    const float* __restrict__ w4, const float* __restrict__ b4,
    const float* __restrict__ w5, const float* __restrict__ b5,
    const float* __restrict__ w6, const float* __restrict__ b6)
{
    __shared__ float zin[8 * F3IN];
    __shared__ float h3 [8 * F3OUT];
    __shared__ float h4 [8 * F4OUT];
    __shared__ float h5 [8 * F5OUT];

    const int bb  = blockIdx.x * 8;
    const int tid = threadIdx.x;

    for (int i = tid; i < 8 * CTX; i += 256) {
        const int s = i >> 6, k = i & 63;
        zin[s * F3IN + k] = c[(size_t)(bb + s) * CTX + k];
    }
    for (int i = tid; i < 8 * H2; i += 256) {
        const int s = i >> 8, k = i & 255;
        zin[s * F3IN + CTX + k] = g_pooled[(size_t)(bb + s) * H2 + k];
    }
    __syncthreads();

    {
        const int j0 = tid * 2;
        const float2 bv = *(const float2*)(b3 + j0);
        float2 acc[8];
        #pragma unroll
        for (int s = 0; s < 8; s++) acc[s] = bv;
        #pragma unroll 4
        for (int k = 0; k < F3IN; k++) {
            const float2 w = *(const float2*)(w3 + k * F3OUT + j0);
            #pragma unroll
            for (int s = 0; s < 8; s++) {
                const float zv = zin[s * F3IN + k];
                acc[s].x = fmaf(zv, w.x, acc[s].x);
                acc[s].y = fmaf(zv, w.y, acc[s].y);
            }
        }
        #pragma unroll
        for (int s = 0; s < 8; s++) {
            float2 r;
            r.x = fmaxf(acc[s].x, 0.f);
            r.y = fmaxf(acc[s].y, 0.f);
            *(float2*)(h3 + s * F3OUT + j0) = r;
        }
    }
    __syncthreads();

    {
        const float bv = b4[tid];
        float acc[8];
        #pragma unroll
        for (int s = 0; s < 8; s++) acc[s] = bv;
        #pragma unroll 8
        for (int k = 0; k < F3OUT; k++) {
            const float w = w4[k * F4OUT + tid];
            #pragma unroll
            for (int s = 0; s < 8; s++) acc[s] = fmaf(h3[s * F3OUT + k], w, acc[s]);
        }
        #pragma unroll
        for (int s = 0; s < 8; s++) h4[s * F4OUT + tid] = fmaxf(acc[s], 0.f);
    }
    __syncthreads();

    {
        const int j  = tid & 127;
        const int sh = tid >> 7;
        const float bv = b5[j];
        float acc[4];
        #pragma unroll
        for (int i = 0; i < 4; i++) acc[i] = bv;
        #pragma unroll 8
        for (int k = 0; k < F4OUT; k++) {
            const float w = w5[k * F5OUT + j];
            #pragma unroll
            for (int i = 0; i < 4; i++)
                acc[i] = fmaf(h4[(sh * 4 + i) * F4OUT + k], w, acc[i]);
        }
        #pragma unroll
        for (int i = 0; i < 4; i++) h5[(sh * 4 + i) * F5OUT + j] = fmaxf(acc[i], 0.f);
    }
    __syncthreads();

    {
        const int s = tid >> 5, j = tid & 31;
        float acc = b6[j];
        #pragma unroll 8
        for (int k = 0; k < F5OUT; k++)
            acc = fmaf(h5[s * F5OUT + k], w6[k * F6OUT + j], acc);
        g_z[(size_t)(bb + s) * F6OUT + j] = fmaxf(acc, 0.f);
    }
}

// ---------------------------------------------------------------------------
// Kernel 3: LSTM rollout with sample-paired f32x2 gates (frozen R10/R11).
// ---------------------------------------------------------------------------
__device__ __forceinline__ float sigmoidf_(float v) { return 1.0f / (1.0f + expf(-v)); }

__global__ __launch_bounds__(256) void lstm_kernel(
    const float* __restrict__ hidden0, const float* __restrict__ cell0,
    const float* __restrict__ wih, const float* __restrict__ whh,
    const float* __restrict__ bih, const float* __restrict__ bhh,
    const float* __restrict__ w10, const float* __restrict__ b10,
    float* __restrict__ out)
{
    __shared__ float hst[NLAYER * 256];
    __shared__ float cst[NLAYER * 256];
    __shared__ float xb [256];
    __shared__ float gtb[4 * 256];
    __shared__ float lsm[8 * 368];
    __shared__ float bsum[NLAYER * 128];

    const int bbase = blockIdx.x * 8;
    const int tid   = threadIdx.x;

    for (int i = tid; i < NLAYER * 256; i += 256) {
        const int l = i >> 8;
        const int p = (i >> 6) & 3;
        const int k = (i >> 1) & 31;
        const int e = i & 1;
        const size_t gofs = (size_t)l * BATCH * HID + (size_t)(bbase + 2 * p + e) * HID + k;
        hst[i] = hidden0[gofs];
        cst[i] = cell0[gofs];
    }
    for (int i = tid; i < 256; i += 256) {
        const int p = (i >> 6) & 3;
        const int k = (i >> 1) & 31;
        const int e = i & 1;
        xb[i] = g_z[(size_t)(bbase + 2 * p + e) * F6OUT + k];
    }
    for (int i = tid; i < NLAYER * 128; i += 256) bsum[i] = bih[i] + bhh[i];
    __syncthreads();

    const int ln   = tid & 31;
    const int w    = tid >> 5;
    const int pw   = w >> 1;
    const int half = w & 1;
    const int j0   = half * 64 + ln * 2;

    const float* inp = xb;

    for (int t = 0; t < TSTEPS; t++) {
        const float* lin = inp;
        for (int l = 0; l < NLAYER; l++) {
            ull gA = pack_dup(bsum[l * 128 + j0]);
            ull gB = pack_dup(bsum[l * 128 + j0 + 1]);
            const float* Wi = wih + (size_t)l * HID * 128;
            const float* Wh = whh + (size_t)l * HID * 128;
            const float* ip = lin + pw * 64;
            const float* hp = hst + l * 256 + pw * 64;
            #pragma unroll 8
            for (int k = 0; k < HID; k++) {
                const float2 wv = *(const float2*)(Wi + k * 128 + j0);
                const ull xx = *(const ull*)(ip + k * 2);
                gA = ffma2(pack_dup(wv.x), xx, gA);
                gB = ffma2(pack_dup(wv.y), xx, gB);
            }
            #pragma unroll 8
            for (int k = 0; k < HID; k++) {
                const float2 wv = *(const float2*)(Wh + k * 128 + j0);
                const ull hh = *(const ull*)(hp + k * 2);
                gA = ffma2(pack_dup(wv.x), hh, gA);
                gB = ffma2(pack_dup(wv.y), hh, gB);
            }
            {
                ulonglong2 st; st.x = gA; st.y = gB;
                *(ulonglong2*)(gtb + pw * 256 + j0 * 2) = st;
            }
            __syncthreads();

            {
                const int s = w, u = ln;
                const int p = s >> 1, e = s & 1;
                const float* gp = gtb + p * 256 + e;
                const float ig = sigmoidf_(gp[u * 2]);
                const float fg = sigmoidf_(gp[(32 + u) * 2]);
                const float gg = tanhf    (gp[(64 + u) * 2]);
                const float og = sigmoidf_(gp[(96 + u) * 2]);
                const int ci = l * 256 + p * 64 + u * 2 + e;
                const float cn = fmaf(fg, cst[ci], ig * gg);
                cst[ci] = cn;
                hst[ci] = og * tanhf(cn);
            }
            __syncthreads();
            lin = hst + l * 256;
        }
        inp = hst + 5 * 256;

        {
            const float* h5v = hst + 5 * 256;
            const int v  = tid;
            const int v2 = tid + 256;
            const bool has2 = (v2 < VOCAB);
            float acc[8], acc2[8];
            const float bv  = b10[v];
            const float bv2 = has2 ? b10[v2] : 0.f;
            #pragma unroll
            for (int s = 0; s < 8; s++) { acc[s] = bv; acc2[s] = bv2; }
            #pragma unroll
            for (int k = 0; k < HID; k++) {
                const float wv  = w10[k * VOCAB + v];
                const float wv2 = has2 ? w10[k * VOCAB + v2] : 0.f;
                #pragma unroll
                for (int s = 0; s < 8; s++) {
                    const float hv = h5v[(s >> 1) * 64 + k * 2 + (s & 1)];
                    acc[s]  = fmaf(hv, wv,  acc[s]);
                    acc2[s] = fmaf(hv, wv2, acc2[s]);
                }
            }
            #pragma unroll
            for (int s = 0; s < 8; s++) {
                lsm[s * 368 + v] = acc[s];
                if (has2) lsm[s * 368 + v2] = acc2[s];
            }
        }
        __syncthreads();

        {
            const int s = w;
            float vals[12];
            #pragma unroll
            for (int i = 0; i < 12; i++) {
                const int idx = ln + i * 32;
                vals[i] = (idx < VOCAB) ? lsm[s * 368 + idx] : -FLT_MAX;
            }
            const int obase = (bbase + s) * (TSTEPS * TOPK) + t * TOPK;
            #pragma unroll
            for (int r = 0; r < TOPK; r++) {
                float bvv = vals[0]; int bi = 0;
                #pragma unroll
                for (int i = 1; i < 12; i++)
                    if (vals[i] > bvv) { bvv = vals[i]; bi = i; }
                int gi = ln + bi * 32;
                #pragma unroll
                for (int off = 16; off; off >>= 1) {
                    const float ov = __shfl_xor_sync(0xffffffffu, bvv, off);
                    const int   oi = __shfl_xor_sync(0xffffffffu, gi,  off);
                    if (ov > bvv || (ov == bvv && oi < gi)) { bvv = ov; gi = oi; }
                }
                if (ln == 0) out[obase + r] = (float)gi;
                if ((gi & 31) == ln) vals[gi >> 5] = -FLT_MAX;
            }
        }
        __syncthreads();
    }
}

// ---------------------------------------------------------------------------
// Host: identify inputs BY SIZE (element count or bytes auto-detected).
// ---------------------------------------------------------------------------
extern "C" void kernel_launch(void* const* d_in, const int* in_sizes, int n_in,
                              void* d_out, int out_size)
{
    const float* C_=0; const float* X_=0; const float* HID0_=0; const float* CELL0_=0;
    const float* W1_=0; const float* B1_=0; const float* W2_=0; const float* B2_=0;
    const float* W3_=0; const float* B3_=0; const float* W4_=0; const float* B4_=0;
    const float* W5_=0; const float* B5_=0; const float* W6_=0; const float* B6_=0;
    const float* BIH_=0; const float* BHH_=0; const float* W10_=0; const float* B10_=0;

    int div = 1;
    for (int i = 0; i < n_in; i++) {
        if (in_sizes[i] == 26214400) { div = 1; break; }
        if (in_sizes[i] == 104857600) { div = 4; break; }
    }

    int n256 = 0, n786 = 0, n768 = 0, n24k = 0;
    int idx24k[2] = {-1, -1};
    int idx_fc10w = -1, idx_fc1w = -1;

    for (int i = 0; i < n_in; i++) {
        const long s = (long)in_sizes[i] / div;
        const float* p = (const float*)d_in[i];
        switch (s) {
            case 262144:   C_  = p; break;
            case 26214400: X_  = p; break;
            case 786432:   if (n786++ == 0) HID0_ = p; else CELL0_ = p; break;
            case 16384:    W1_ = p; idx_fc1w = i; break;
            case 256:      { if (n256 == 0) B1_ = p; else if (n256 == 1) B2_ = p;
                             else B4_ = p; n256++; } break;
            case 65536:    W2_ = p; break;
            case 163840:   W3_ = p; break;
            case 512:      B3_ = p; break;
            case 131072:   W4_ = p; break;
            case 32768:    W5_ = p; break;
            case 128:      B5_ = p; break;
            case 4096:     W6_ = p; break;
            case 32:       B6_ = p; break;
            case 24576:    if (n24k < 2) idx24k[n24k] = i; n24k++; break;
            case 768:      if (n768++ == 0) BIH_ = p; else BHH_ = p; break;
            case 11552:    W10_ = p; idx_fc10w = i; break;
            case 361:      B10_ = p; break;
            default: break; // particle_size scalar etc.
        }
    }

    const float* WIH_ = 0; const float* WHH_ = 0;
    if (n24k >= 2) {
        const bool alpha = (idx_fc10w >= 0 && idx_fc1w >= 0 && idx_fc10w < idx_fc1w);
        const int wih_idx = alpha ? idx24k[1] : idx24k[0];
        const int whh_idx = alpha ? idx24k[0] : idx24k[1];
        WIH_ = (const float*)d_in[wih_idx];
        WHH_ = (const float*)d_in[whh_idx];
    }

    if (!C_ || !X_ || !HID0_ || !CELL0_ || !W1_ || !B1_ || !W2_ || !B2_ ||
        !W3_ || !B3_ || !W4_ || !B4_ || !W5_ || !B5_ || !W6_ || !B6_ ||
        !WIH_ || !WHH_ || !BIH_ || !BHH_ || !W10_ || !B10_) {
        C_    = (const float*)d_in[0];  X_    = (const float*)d_in[1];
        HID0_ = (const float*)d_in[2];  CELL0_= (const float*)d_in[3];
        W1_   = (const float*)d_in[4];  B1_   = (const float*)d_in[5];
        W2_   = (const float*)d_in[6];  B2_   = (const float*)d_in[7];
        W3_   = (const float*)d_in[8];  B3_   = (const float*)d_in[9];
        W4_   = (const float*)d_in[10]; B4_   = (const float*)d_in[11];
        W5_   = (const float*)d_in[12]; B5_   = (const float*)d_in[13];
        W6_   = (const float*)d_in[14]; B6_   = (const float*)d_in[15];
        WIH_  = (const float*)d_in[16]; WHH_  = (const float*)d_in[17];
        BIH_  = (const float*)d_in[18]; BHH_  = (const float*)d_in[19];
        W10_  = (const float*)d_in[20]; B10_  = (const float*)d_in[21];
    }
    (void)out_size;

    cudaFuncSetAttribute(enc_tf,
                         cudaFuncAttributeMaxDynamicSharedMemorySize,
                         ENC_SMEM_BYTES);

    prep_tf<<<256, 256>>>(W1_, W2_);
    enc_tf<<<BATCH, 256, ENC_SMEM_BYTES>>>(X_, B1_, B2_);
    head_kernel<<<BATCH / 8, 256>>>(C_, W3_, B3_, W4_, B4_, W5_, B5_, W6_, B6_);
    lstm_kernel<<<BATCH / 8, 256>>>(HID0_, CELL0_, WIH_, WHH_, BIH_, BHH_,
                                    W10_, B10_, (float*)d_out);
}

// round 17
// speedup vs baseline: 2.1881x; 2.1881x over previous
#include <cuda_runtime.h>
#include <math.h>
#include <float.h>

#define BATCH   4096
#define NPART   100
#define PSIZE   64
#define CTX     64
#define H1      256
#define H2      256
#define F3IN    320
#define F3OUT   512
#define F4OUT   256
#define F5OUT   128
#define F6OUT   32
#define HID     32
#define NLAYER  6
#define VOCAB   361
#define TSTEPS  24
#define TOPK    8

typedef unsigned long long ull;

// scratch (device globals: allowed; no runtime allocation)
__device__ float g_pooled[BATCH * H2];   // 4 MB
__device__ float g_z[BATCH * F6OUT];     // 0.5 MB

// ---------------- f32x2 packed helpers (Blackwell FFMA2 path) --------------
__device__ __forceinline__ ull ffma2(ull a, ull b, ull c) {
    ull d;
    asm("fma.rn.f32x2 %0, %1, %2, %3;" : "=l"(d) : "l"(a), "l"(b), "l"(c));
    return d;
}
__device__ __forceinline__ ull pack_dup(float v) {
    ull d;
    unsigned r = __float_as_uint(v);
    asm("mov.b64 %0, {%1, %2};" : "=l"(d) : "r"(r), "r"(r));
    return d;
}
__device__ __forceinline__ float2 unpack2(ull v) {
    unsigned lo, hi;
    asm("mov.b64 {%0, %1}, %2;" : "=r"(lo), "=r"(hi) : "l"(v));
    return make_float2(__uint_as_float(lo), __uint_as_float(hi));
}

// ---------------------------------------------------------------------------
// Kernel 1: particle-paired encoder (R11 verbatim — best measured: 1.655ms).
// ---------------------------------------------------------------------------
#define XROWF 104
#define HROWF 24
#define ENC_SMEM_BYTES ((64 * XROWF + 256 * HROWF) * 4)   // 51200

template<int PG>
__device__ __forceinline__ void load5(const float* row, int base, ull* px)
{
    const float* p = row + base * 2;
    if (PG == 0) {
        const ulonglong2 q0 = *(const ulonglong2*)(p);
        const ulonglong2 q1 = *(const ulonglong2*)(p + 4);
        const ull q2 = *(const ull*)(p + 8);
        px[0] = q0.x; px[1] = q0.y; px[2] = q1.x; px[3] = q1.y; px[4] = q2;
    } else {
        const ull q0 = *(const ull*)(p);
        const ulonglong2 q1 = *(const ulonglong2*)(p + 2);
        const ulonglong2 q2 = *(const ulonglong2*)(p + 6);
        px[0] = q0; px[1] = q1.x; px[2] = q1.y; px[3] = q2.x; px[4] = q2.y;
    }
}

template<int PG>
__device__ __forceinline__ void enc_chunk(
    const float* __restrict__ w1, const ull b1A, const ull b1B,
    const float* __restrict__ w2, const ull b2A, const ull b2B,
    const float* xpp, float* hpp,
    int c, int jA, int jB, float& pool0, float& pool1)
{
    const int cpp = c * 10 + PG * 5;
    const int lpp = PG * 5;

    ull aA[5], aB[5];
    #pragma unroll
    for (int i = 0; i < 5; i++) { aA[i] = b1A; aB[i] = b1B; }

    #pragma unroll 4
    for (int k = 0; k < PSIZE; k++) {
        const ull wAd = pack_dup(w1[k * H1 + jA]);
        const ull wBd = pack_dup(w1[k * H1 + jB]);
        ull px[5];
        load5<PG>(xpp + k * XROWF, cpp, px);
        #pragma unroll
        for (int i = 0; i < 5; i++) {
            aA[i] = ffma2(px[i], wAd, aA[i]);
            aB[i] = ffma2(px[i], wBd, aB[i]);
        }
    }
    #pragma unroll
    for (int i = 0; i < 5; i++) {
        const float2 vA = unpack2(aA[i]);
        const float2 vB = unpack2(aB[i]);
        *(float2*)(hpp + jA * HROWF + (lpp + i) * 2) =
            make_float2(fmaxf(vA.x, 0.f), fmaxf(vA.y, 0.f));
        *(float2*)(hpp + jB * HROWF + (lpp + i) * 2) =
            make_float2(fmaxf(vB.x, 0.f), fmaxf(vB.y, 0.f));
    }
    __syncthreads();

    ull cA[5], cB[5];
    #pragma unroll
    for (int i = 0; i < 5; i++) { cA[i] = b2A; cB[i] = b2B; }

    #pragma unroll 4
    for (int k = 0; k < H1; k++) {
        const ull wAd = pack_dup(w2[k * H1 + jA]);
        const ull wBd = pack_dup(w2[k * H1 + jB]);
        ull ph[5];
        load5<PG>(hpp + k * HROWF, lpp, ph);
        #pragma unroll
        for (int i = 0; i < 5; i++) {
            cA[i] = ffma2(ph[i], wAd, cA[i]);
            cB[i] = ffma2(ph[i], wBd, cB[i]);
        }
    }
    #pragma unroll
    for (int i = 0; i < 5; i++) {
        const float2 vA = unpack2(cA[i]);
        const float2 vB = unpack2(cB[i]);
        pool0 += fmaxf(vA.x, 0.f) + fmaxf(vA.y, 0.f);
        pool1 += fmaxf(vB.x, 0.f) + fmaxf(vB.y, 0.f);
    }
    __syncthreads();
}

__global__ __launch_bounds__(256) void enc_kernel(
    const float* __restrict__ x,
    const float* __restrict__ w1, const float* __restrict__ b1,
    const float* __restrict__ w2, const float* __restrict__ b2)
{
    extern __shared__ float sm[];
    float* xpp = sm;
    float* hpp = sm + 64 * XROWF;

    const int b   = blockIdx.x;
    const int tid = threadIdx.x;

    for (int i = tid; i < NPART * PSIZE; i += 256) {
        const int p = i >> 6, k = i & 63;
        xpp[k * XROWF + (p >> 1) * 2 + (p & 1)] = x[(size_t)b * (NPART * PSIZE) + i];
    }
    __syncthreads();

    const int w  = tid >> 5;
    const int ln = tid & 31;
    const int jb = (w & 3) * 64;
    const int pg = w >> 2;
    const int jA = jb + ln;
    const int jB = jb + 32 + ln;

    const ull b1A = pack_dup(b1[jA]);
    const ull b1B = pack_dup(b1[jB]);
    const ull b2A = pack_dup(b2[jA]);
    const ull b2B = pack_dup(b2[jB]);

    float pool0 = 0.f, pool1 = 0.f;

    if (pg == 0) {
        for (int c = 0; c < 5; c++)
            enc_chunk<0>(w1, b1A, b1B, w2, b2A, b2B, xpp, hpp, c, jA, jB, pool0, pool1);
    } else {
        for (int c = 0; c < 5; c++)
            enc_chunk<1>(w1, b1A, b1B, w2, b2A, b2B, xpp, hpp, c, jA, jB, pool0, pool1);
    }

    float* red = sm;
    red[pg * H1 + jA] = pool0;
    red[pg * H1 + jB] = pool1;
    __syncthreads();
    g_pooled[(size_t)b * H2 + tid] = (red[tid] + red[H1 + tid]) * 0.01f;
}

// ---------------------------------------------------------------------------
// Kernel 2: fc3..fc6 head. 8 samples per CTA, 256 threads. (frozen R11)
// ---------------------------------------------------------------------------
__global__ __launch_bounds__(256) void head_kernel(
    const float* __restrict__ c,
    const float* __restrict__ w3, const float* __restrict__ b3,
    const float* __restrict__ w4, const float* __restrict__ b4,
    const float* __restrict__ w5, const float* __restrict__ b5,
    const float* __restrict__ w6, const float* __restrict__ b6)
{
    __shared__ float zin[8 * F3IN];
    __shared__ float h3 [8 * F3OUT];
    __shared__ float h4 [8 * F4OUT];
    __shared__ float h5 [8 * F5OUT];

    const int bb  = blockIdx.x * 8;
    const int tid = threadIdx.x;

    for (int i = tid; i < 8 * CTX; i += 256) {
        const int s = i >> 6, k = i & 63;
        zin[s * F3IN + k] = c[(size_t)(bb + s) * CTX + k];
    }
    for (int i = tid; i < 8 * H2; i += 256) {
        const int s = i >> 8, k = i & 255;
        zin[s * F3IN + CTX + k] = g_pooled[(size_t)(bb + s) * H2 + k];
    }
    __syncthreads();

    {
        const int j0 = tid * 2;
        const float2 bv = *(const float2*)(b3 + j0);
        float2 acc[8];
        #pragma unroll
        for (int s = 0; s < 8; s++) acc[s] = bv;
        #pragma unroll 4
        for (int k = 0; k < F3IN; k++) {
            const float2 w = *(const float2*)(w3 + k * F3OUT + j0);
            #pragma unroll
            for (int s = 0; s < 8; s++) {
                const float zv = zin[s * F3IN + k];
                acc[s].x = fmaf(zv, w.x, acc[s].x);
                acc[s].y = fmaf(zv, w.y, acc[s].y);
            }
        }
        #pragma unroll
        for (int s = 0; s < 8; s++) {
            float2 r;
            r.x = fmaxf(acc[s].x, 0.f);
            r.y = fmaxf(acc[s].y, 0.f);
            *(float2*)(h3 + s * F3OUT + j0) = r;
        }
    }
    __syncthreads();

    {
        const float bv = b4[tid];
        float acc[8];
        #pragma unroll
        for (int s = 0; s < 8; s++) acc[s] = bv;
        #pragma unroll 8
        for (int k = 0; k < F3OUT; k++) {
            const float w = w4[k * F4OUT + tid];
            #pragma unroll
            for (int s = 0; s < 8; s++) acc[s] = fmaf(h3[s * F3OUT + k], w, acc[s]);
        }
        #pragma unroll
        for (int s = 0; s < 8; s++) h4[s * F4OUT + tid] = fmaxf(acc[s], 0.f);
    }
    __syncthreads();

    {
        const int j  = tid & 127;
        const int sh = tid >> 7;
        const float bv = b5[j];
        float acc[4];
        #pragma unroll
        for (int i = 0; i < 4; i++) acc[i] = bv;
        #pragma unroll 8
        for (int k = 0; k < F4OUT; k++) {
            const float w = w5[k * F5OUT + j];
            #pragma unroll
            for (int i = 0; i < 4; i++)
                acc[i] = fmaf(h4[(sh * 4 + i) * F4OUT + k], w, acc[i]);
        }
        #pragma unroll
        for (int i = 0; i < 4; i++) h5[(sh * 4 + i) * F5OUT + j] = fmaxf(acc[i], 0.f);
    }
    __syncthreads();

    {
        const int s = tid >> 5, j = tid & 31;
        float acc = b6[j];
        #pragma unroll 8
        for (int k = 0; k < F5OUT; k++)
            acc = fmaf(h5[s * F5OUT + k], w6[k * F6OUT + j], acc);
        g_z[(size_t)(bb + s) * F6OUT + j] = fmaxf(acc, 0.f);
    }
}

// ---------------------------------------------------------------------------
// Kernel 3 (v5): LSTM rollout, 16 samples/CTA (8 pairs), 256 thr, grid 256.
// State layout [l][k][pair][e]: one LDS.128 per k serves 4 samples' gates.
// Warp (pq = w>>1, half = w&1) computes 64 gate cols for pairs 2pq, 2pq+1.
// Per-sample fma chains bitwise identical to R11 (bias, asc-k Wi, asc-k Wh).
// ---------------------------------------------------------------------------
__device__ __forceinline__ float sigmoidf_(float v) { return 1.0f / (1.0f + expf(-v)); }

// dynamic smem layout (floats):
//   hst 0..3071  cst 3072..6143  xb 6144..6655  bsum 6656..7423
//   gtb 7424..9471  lsm 9472..15359
#define LSTM_SMEM_BYTES (15360 * 4)

__global__ __launch_bounds__(256) void lstm_kernel(
    const float* __restrict__ hidden0, const float* __restrict__ cell0,
    const float* __restrict__ wih, const float* __restrict__ whh,
    const float* __restrict__ bih, const float* __restrict__ bhh,
    const float* __restrict__ w10, const float* __restrict__ b10,
    float* __restrict__ out)
{
    extern __shared__ float lsmem[];
    float* hst  = lsmem;            // [l][k][16]  (k*16 + 2p+e)
    float* cst  = lsmem + 3072;
    float* xb   = lsmem + 6144;     // [k][16]
    float* bsum = lsmem + 6656;
    float* gtb  = lsmem + 7424;     // [p][col][e]
    float* lsm  = lsmem + 9472;     // [16][368]

    const int bbase = blockIdx.x * 16;
    const int tid   = threadIdx.x;

    for (int i = tid; i < NLAYER * 512; i += 256) {
        const int l  = i >> 9;
        const int k  = (i >> 4) & 31;
        const int pe = i & 15;
        const size_t gofs = (size_t)l * BATCH * HID + (size_t)(bbase + pe) * HID + k;
        hst[i] = hidden0[gofs];
        cst[i] = cell0[gofs];
    }
    for (int i = tid; i < 512; i += 256) {
        const int k = i >> 4, pe = i & 15;
        xb[i] = g_z[(size_t)(bbase + pe) * F6OUT + k];
    }
    for (int i = tid; i < NLAYER * 128; i += 256) bsum[i] = bih[i] + bhh[i];
    __syncthreads();

    const int ln   = tid & 31;
    const int w    = tid >> 5;
    const int pq   = w >> 1;            // pair-quad: pairs 2pq, 2pq+1
    const int half = w & 1;
    const int j0   = half * 64 + ln * 2;

    const float* inp = xb;   // scan carry ([k][16] layout)

    for (int t = 0; t < TSTEPS; t++) {
        const float* lin = inp;
        for (int l = 0; l < NLAYER; l++) {
            ull gA0 = pack_dup(bsum[l * 128 + j0]);
            ull gB0 = pack_dup(bsum[l * 128 + j0 + 1]);
            ull gA1 = gA0, gB1 = gB0;
            const float* Wi = wih + (size_t)l * HID * 128;
            const float* Wh = whh + (size_t)l * HID * 128;
            const float* hp = hst + l * 512;
            #pragma unroll 8
            for (int k = 0; k < HID; k++) {
                const float2 wv = *(const float2*)(Wi + k * 128 + j0);
                const ulonglong2 xx = *(const ulonglong2*)(lin + k * 16 + 4 * pq);
                const ull wx = pack_dup(wv.x), wy = pack_dup(wv.y);
                gA0 = ffma2(wx, xx.x, gA0); gA1 = ffma2(wx, xx.y, gA1);
                gB0 = ffma2(wy, xx.x, gB0); gB1 = ffma2(wy, xx.y, gB1);
            }
            #pragma unroll 8
            for (int k = 0; k < HID; k++) {
                const float2 wv = *(const float2*)(Wh + k * 128 + j0);
                const ulonglong2 hh = *(const ulonglong2*)(hp + k * 16 + 4 * pq);
                const ull wx = pack_dup(wv.x), wy = pack_dup(wv.y);
                gA0 = ffma2(wx, hh.x, gA0); gA1 = ffma2(wx, hh.y, gA1);
                gB0 = ffma2(wy, hh.x, gB0); gB1 = ffma2(wy, hh.y, gB1);
            }
            {
                ulonglong2 s0; s0.x = gA0; s0.y = gB0;
                *(ulonglong2*)(gtb + (2 * pq) * 256 + j0 * 2) = s0;
                ulonglong2 s1; s1.x = gA1; s1.y = gB1;
                *(ulonglong2*)(gtb + (2 * pq + 1) * 256 + j0 * 2) = s1;
            }
            __syncthreads();

            // cell/hidden update: warp w handles samples w and w+8, lane = unit
            #pragma unroll
            for (int sv = 0; sv < 2; sv++) {
                const int s = w + 8 * sv;
                const int p = s >> 1, e = s & 1;
                const int u = ln;
                const float* gp = gtb + p * 256 + e;
                const float ig = sigmoidf_(gp[u * 2]);
                const float fg = sigmoidf_(gp[(32 + u) * 2]);
                const float gg = tanhf    (gp[(64 + u) * 2]);
                const float og = sigmoidf_(gp[(96 + u) * 2]);
                const int ci = l * 512 + u * 16 + p * 2 + e;
                const float cn = fmaf(fg, cst[ci], ig * gg);
                cst[ci] = cn;
                hst[ci] = og * tanhf(cn);
            }
            __syncthreads();
            lin = hst + l * 512;
        }
        inp = hst + 5 * 512;   // carry to next timestep

        // logits: thread owns vocab cols tid, tid+256; sample-paired ull accs
        {
            const float* h5v = hst + 5 * 512;
            const int v  = tid;
            const int v2 = tid + 256;
            const bool has2 = (v2 < VOCAB);
            ull acc[8], acc2[8];
            {
                const ull bv  = pack_dup(b10[v]);
                const ull bv2 = has2 ? pack_dup(b10[v2]) : 0ULL;
                #pragma unroll
                for (int p = 0; p < 8; p++) { acc[p] = bv; acc2[p] = bv2; }
            }
            #pragma unroll 2
            for (int k = 0; k < HID; k++) {
                const ull wv  = pack_dup(w10[k * VOCAB + v]);
                const ull wv2 = has2 ? pack_dup(w10[k * VOCAB + v2]) : 0ULL;
                #pragma unroll
                for (int p = 0; p < 8; p++) {
                    const ull hh = *(const ull*)(h5v + k * 16 + p * 2);
                    acc[p]  = ffma2(hh, wv,  acc[p]);
                    acc2[p] = ffma2(hh, wv2, acc2[p]);
                }
            }
            #pragma unroll
            for (int p = 0; p < 8; p++) {
                const float2 va = unpack2(acc[p]);
                lsm[(2 * p) * 368 + v]     = va.x;
                lsm[(2 * p + 1) * 368 + v] = va.y;
                if (has2) {
                    const float2 vb = unpack2(acc2[p]);
                    lsm[(2 * p) * 368 + v2]     = vb.x;
                    lsm[(2 * p + 1) * 368 + v2] = vb.y;
                }
            }
        }
        __syncthreads();

        // top-8: warp w handles samples w and w+8 (R11 routine x2)
        for (int sv = 0; sv < 2; sv++) {
            const int s = w + 8 * sv;
            float vals[12];
            #pragma unroll
            for (int i = 0; i < 12; i++) {
                const int idx = ln + i * 32;
                vals[i] = (idx < VOCAB) ? lsm[s * 368 + idx] : -FLT_MAX;
            }
            const int obase = (bbase + s) * (TSTEPS * TOPK) + t * TOPK;
            #pragma unroll
            for (int r = 0; r < TOPK; r++) {
                float bvv = vals[0]; int bi = 0;
                #pragma unroll
                for (int i = 1; i < 12; i++)
                    if (vals[i] > bvv) { bvv = vals[i]; bi = i; }
                int gi = ln + bi * 32;
                #pragma unroll
                for (int off = 16; off; off >>= 1) {
                    const float ov = __shfl_xor_sync(0xffffffffu, bvv, off);
                    const int   oi = __shfl_xor_sync(0xffffffffu, gi,  off);
                    if (ov > bvv || (ov == bvv && oi < gi)) { bvv = ov; gi = oi; }
                }
                if (ln == 0) out[obase + r] = (float)gi;
                if ((gi & 31) == ln) vals[gi >> 5] = -FLT_MAX;
            }
        }
        __syncthreads();
    }
}

// ---------------------------------------------------------------------------
// Host: identify inputs BY SIZE (element count or bytes auto-detected).
// ---------------------------------------------------------------------------
extern "C" void kernel_launch(void* const* d_in, const int* in_sizes, int n_in,
                              void* d_out, int out_size)
{
    const float* C_=0; const float* X_=0; const float* HID0_=0; const float* CELL0_=0;
    const float* W1_=0; const float* B1_=0; const float* W2_=0; const float* B2_=0;
    const float* W3_=0; const float* B3_=0; const float* W4_=0; const float* B4_=0;
    const float* W5_=0; const float* B5_=0; const float* W6_=0; const float* B6_=0;
    const float* BIH_=0; const float* BHH_=0; const float* W10_=0; const float* B10_=0;

    int div = 1;
    for (int i = 0; i < n_in; i++) {
        if (in_sizes[i] == 26214400) { div = 1; break; }
        if (in_sizes[i] == 104857600) { div = 4; break; }
    }

    int n256 = 0, n786 = 0, n768 = 0, n24k = 0;
    int idx24k[2] = {-1, -1};
    int idx_fc10w = -1, idx_fc1w = -1;

    for (int i = 0; i < n_in; i++) {
        const long s = (long)in_sizes[i] / div;
        const float* p = (const float*)d_in[i];
        switch (s) {
            case 262144:   C_  = p; break;
            case 26214400: X_  = p; break;
            case 786432:   if (n786++ == 0) HID0_ = p; else CELL0_ = p; break;
            case 16384:    W1_ = p; idx_fc1w = i; break;
            case 256:      { if (n256 == 0) B1_ = p; else if (n256 == 1) B2_ = p;
                             else B4_ = p; n256++; } break;
            case 65536:    W2_ = p; break;
            case 163840:   W3_ = p; break;
            case 512:      B3_ = p; break;
            case 131072:   W4_ = p; break;
            case 32768:    W5_ = p; break;
            case 128:      B5_ = p; break;
            case 4096:     W6_ = p; break;
            case 32:       B6_ = p; break;
            case 24576:    if (n24k < 2) idx24k[n24k] = i; n24k++; break;
            case 768:      if (n768++ == 0) BIH_ = p; else BHH_ = p; break;
            case 11552:    W10_ = p; idx_fc10w = i; break;
            case 361:      B10_ = p; break;
            default: break; // particle_size scalar etc.
        }
    }

    const float* WIH_ = 0; const float* WHH_ = 0;
    if (n24k >= 2) {
        const bool alpha = (idx_fc10w >= 0 && idx_fc1w >= 0 && idx_fc10w < idx_fc1w);
        const int wih_idx = alpha ? idx24k[1] : idx24k[0];
        const int whh_idx = alpha ? idx24k[0] : idx24k[1];
        WIH_ = (const float*)d_in[wih_idx];
        WHH_ = (const float*)d_in[whh_idx];
    }

    if (!C_ || !X_ || !HID0_ || !CELL0_ || !W1_ || !B1_ || !W2_ || !B2_ ||
        !W3_ || !B3_ || !W4_ || !B4_ || !W5_ || !B5_ || !W6_ || !B6_ ||
        !WIH_ || !WHH_ || !BIH_ || !BHH_ || !W10_ || !B10_) {
        C_    = (const float*)d_in[0];  X_    = (const float*)d_in[1];
        HID0_ = (const float*)d_in[2];  CELL0_= (const float*)d_in[3];
        W1_   = (const float*)d_in[4];  B1_   = (const float*)d_in[5];
        W2_   = (const float*)d_in[6];  B2_   = (const float*)d_in[7];
        W3_   = (const float*)d_in[8];  B3_   = (const float*)d_in[9];
        W4_   = (const float*)d_in[10]; B4_   = (const float*)d_in[11];
        W5_   = (const float*)d_in[12]; B5_   = (const float*)d_in[13];
        W6_   = (const float*)d_in[14]; B6_   = (const float*)d_in[15];
        WIH_  = (const float*)d_in[16]; WHH_  = (const float*)d_in[17];
        BIH_  = (const float*)d_in[18]; BHH_  = (const float*)d_in[19];
        W10_  = (const float*)d_in[20]; B10_  = (const float*)d_in[21];
    }
    (void)out_size;

    cudaFuncSetAttribute(enc_kernel,
                         cudaFuncAttributeMaxDynamicSharedMemorySize,
                         ENC_SMEM_BYTES);
    cudaFuncSetAttribute(lstm_kernel,
                         cudaFuncAttributeMaxDynamicSharedMemorySize,
                         LSTM_SMEM_BYTES);

    enc_kernel<<<BATCH, 256, ENC_SMEM_BYTES>>>(X_, W1_, B1_, W2_, B2_);
    head_kernel<<<BATCH / 8, 256>>>(C_, W3_, B3_, W4_, B4_, W5_, B5_, W6_, B6_);
    lstm_kernel<<<BATCH / 16, 256, LSTM_SMEM_BYTES>>>(HID0_, CELL0_, WIH_, WHH_,
                                                      BIH_, BHH_, W10_, B10_,
                                                      (float*)d_out);
}